// round 13
// baseline (speedup 1.0000x reference)
#include <cuda_runtime.h>
#include <cstdint>

// Problem constants
#define TQ     8192      // T/2 output positions
#define DM     768       // model dim
#define NBINS  1024      // codebook entries
#define TIN    16384     // input T
#define KCONV  1536      // conv GEMM K = D*2
#define NKB1   96        // conv K chunks (1536/16)
#define NKB2   48        // dist K chunks (768/16)

#define CONV_TILES  384              // 64 m-tiles x 6 n-tiles
#define DIST_TILES  512              // 64 m-tiles x 8 n-tiles
#define TOTAL_TILES (CONV_TILES + DIST_TILES)
#define NWORKERS    296              // 148 SMs x 2 CTAs

typedef unsigned int u32;

// ---------------------------------------------------------------------------
// Scratch (__device__ globals; no allocation).
// Operands pre-split to TF32 (hi, mid) and pre-arranged in mma.m16n8k8
// fragment order; GEMM staging is a contiguous cp.async copy.
// Per (tile, kb) block: 4096 floats = [part(2)][2048 fragment-ordered].
// ---------------------------------------------------------------------------
__device__ float g_Afrag[64 * NKB1 * 4096];   // conv A   (100 MB)
__device__ float g_Wfrag [6 * NKB1 * 4096];   // conv B   (9.4 MB)
__device__ float g_Xfrag[64 * NKB2 * 4096];   // dist A = conv output (50 MB)
__device__ float g_CBfrag[8 * NKB2 * 4096];   // dist B   (6.3 MB)
__device__ float g_cnorm[NBINS];
__device__ float g_pmin[TQ * 8];
__device__ int   g_pidx[TQ * 8];
__device__ int   g_ctr;                        // work-queue counter
__device__ int   g_done[64];                   // conv completions per m-tile

// ---------------------------------------------------------------------------
// Helpers (family-agnostic PTX only — build target is plain sm_103)
// ---------------------------------------------------------------------------
__device__ __forceinline__ void tf32_split(float x, float& h, float& m) {
    u32 hu, mu;
    asm("cvt.rna.tf32.f32 %0, %1;" : "=r"(hu) : "f"(x));
    h = __uint_as_float(hu);
    float r = x - h;
    asm("cvt.rna.tf32.f32 %0, %1;" : "=r"(mu) : "f"(r));
    m = __uint_as_float(mu);
}

__device__ __forceinline__ void mma8(float* d, const u32* a, const u32* b) {
    asm volatile(
        "mma.sync.aligned.m16n8k8.row.col.f32.tf32.tf32.f32 "
        "{%0,%1,%2,%3}, {%4,%5,%6,%7}, {%8,%9}, {%0,%1,%2,%3};"
        : "+f"(d[0]), "+f"(d[1]), "+f"(d[2]), "+f"(d[3])
        : "r"(a[0]), "r"(a[1]), "r"(a[2]), "r"(a[3]), "r"(b[0]), "r"(b[1]));
}

__device__ __forceinline__ u32 smem_u32(const void* p) {
    u32 a;
    asm("{ .reg .u64 t; cvta.to.shared.u64 t, %1; cvt.u32.u64 %0, t; }"
        : "=r"(a) : "l"(p));
    return a;
}
__device__ __forceinline__ void cpasync16(u32 dst, const void* src) {
    asm volatile("cp.async.cg.shared.global [%0], [%1], 16;"
                 :: "r"(dst), "l"(src) : "memory");
}
#define CP_COMMIT() asm volatile("cp.async.commit_group;" ::: "memory")
#define CP_WAIT(n)  asm volatile("cp.async.wait_group %0;" :: "n"(n) : "memory")

// A-fragment offset for (m 0..127, k 0..15)
__device__ __forceinline__ int a_off(int m, int k) {
    return ((k >> 3) * 8 + (m >> 4)) * 128
         + ((((m & 7) << 2) | (k & 3)) << 2)
         + (((k >> 2) & 1) << 1) + ((m >> 3) & 1);
}
// B-fragment offset for (n 0..127, k 0..15)
__device__ __forceinline__ int b_off(int n, int k) {
    return (((k >> 3) & 1) << 10) + ((n >> 3) << 6)
         + ((((n & 7) << 2) | (k & 3)) << 1) + ((k >> 2) & 1);
}

// ---------------------------------------------------------------------------
// Unified pre-pass kernel (grid 1280 x 256, partitioned by block range):
//   b 0..63    : splitW      b 64..111  : splitCB
//   b 112..239 : cnorm       b 240..1279: splitA
// Block 0 also resets the work-queue + dependency counters (every replay!).
// ---------------------------------------------------------------------------
__global__ void prep_kernel(const float* __restrict__ W,
                            const float* __restrict__ cb,
                            const float* __restrict__ ssl) {
    const int b = blockIdx.x, tid = threadIdx.x;
    if (b == 0) {
        if (tid == 0) g_ctr = 0;
        if (tid < 64) g_done[tid] = 0;
    }
    if (b < 64) {                                      // splitW
        for (int i = b * 256 + tid; i < DM * KCONV; i += 64 * 256) {
            int n = i / KCONV, k = i % KCONV;
            float h, m; tf32_split(W[i], h, m);
            size_t base = ((size_t)(n >> 7) * NKB1 + (k >> 4)) * 4096;
            int off = b_off(n & 127, k & 15);
            g_Wfrag[base + off]        = h;
            g_Wfrag[base + 2048 + off] = m;
        }
    } else if (b < 112) {                              // splitCB
        for (int i = (b - 64) * 256 + tid; i < NBINS * DM; i += 48 * 256) {
            int n = i / DM, k = i % DM;
            float h, m; tf32_split(cb[i], h, m);
            size_t base = ((size_t)(n >> 7) * NKB2 + (k >> 4)) * 4096;
            int off = b_off(n & 127, k & 15);
            g_CBfrag[base + off]        = h;
            g_CBfrag[base + 2048 + off] = m;
        }
    } else if (b < 240) {                              // cnorm (warp per row)
        int row = (b - 112) * 8 + (tid >> 5);
        int lane = tid & 31;
        if (row < NBINS) {
            const float* r = cb + row * DM;
            float s = 0.f;
            for (int i = lane; i < DM; i += 32) { float v = r[i]; s += v * v; }
            #pragma unroll
            for (int o = 16; o; o >>= 1) s += __shfl_xor_sync(0xffffffffu, s, o);
            if (lane == 0) g_cnorm[row] = s;
        }
    } else {                                           // splitA
        for (int i = (b - 240) * 256 + tid; i < DM * TQ; i += 1040 * 256) {
            int d = i / TQ, m = i % TQ;
            const float2 v = *(const float2*)(ssl + (size_t)d * TIN + 2 * m);
            size_t mbase = (size_t)(m >> 7) * NKB1 * 4096;
            #pragma unroll
            for (int tap = 0; tap < 2; ++tap) {
                int k = 2 * d + tap;
                float h, md; tf32_split(tap ? v.y : v.x, h, md);
                size_t base = mbase + (size_t)(k >> 4) * 4096;
                int off = a_off(m & 127, k & 15);
                g_Afrag[base + off]        = h;
                g_Afrag[base + 2048 + off] = md;
            }
        }
    }
}

// ---------------------------------------------------------------------------
// One BK=16 chunk, 3-pass TF32 split, warp tile 64x32.
// ---------------------------------------------------------------------------
__device__ __forceinline__ void mma_chunk(const float* As, const float* Bs,
                                          float acc[4][4][4], int mtb, int ntb,
                                          int lane) {
    #pragma unroll
    for (int k8 = 0; k8 < 2; ++k8) {
        uint4 ah[4], am[4]; uint2 bh[4], bm[4];
        #pragma unroll
        for (int t = 0; t < 4; ++t) {
            int base = (k8 * 8 + mtb + t) * 128 + lane * 4;
            ah[t] = *(const uint4*)&As[base];
            am[t] = *(const uint4*)&As[2048 + base];
        }
        #pragma unroll
        for (int t = 0; t < 4; ++t) {
            int base = k8 * 1024 + (ntb + t) * 64 + lane * 2;
            bh[t] = *(const uint2*)&Bs[base];
            bm[t] = *(const uint2*)&Bs[2048 + base];
        }
        #pragma unroll
        for (int i = 0; i < 4; ++i)
            #pragma unroll
            for (int j = 0; j < 4; ++j)
                mma8(acc[i][j], (const u32*)&ah[i], (const u32*)&bh[j]);
        #pragma unroll
        for (int i = 0; i < 4; ++i)
            #pragma unroll
            for (int j = 0; j < 4; ++j)
                mma8(acc[i][j], (const u32*)&ah[i], (const u32*)&bm[j]);
        #pragma unroll
        for (int i = 0; i < 4; ++i)
            #pragma unroll
            for (int j = 0; j < 4; ++j)
                mma8(acc[i][j], (const u32*)&am[i], (const u32*)&bh[j]);
    }
}

#define STAGES 3
#define STAGE_FLOATS 8192            // A 4096 + B 4096
#define STAGE_BYTES  32768
#define SMEM_BYTES   (STAGES * STAGE_BYTES)   // 96 KB -> 2 CTAs/SM

__device__ __forceinline__ void issue_chunk(u32 smb, int s, int tid,
                                            const float* Ablk, const float* Bblk,
                                            int kb) {
    u32 sb = smb + s * STAGE_BYTES;
    const char* asrc = (const char*)Ablk + (size_t)kb * 16384;
    const char* bsrc = (const char*)Bblk + (size_t)kb * 16384;
    #pragma unroll
    for (int it = 0; it < 4; ++it) {
        int idx = tid + it * 256;
        cpasync16(sb + idx * 16,         asrc + (size_t)idx * 16);
        cpasync16(sb + 16384 + idx * 16, bsrc + (size_t)idx * 16);
    }
    CP_COMMIT();
}

template <int NKB>
__device__ __forceinline__ void run_mainloop(u32 smb, float* smf, int tid,
                                             int lane, int mtb, int ntb,
                                             const float* Ablk, const float* Bblk,
                                             float acc[4][4][4]) {
    #pragma unroll
    for (int s = 0; s < STAGES - 1; ++s) issue_chunk(smb, s, tid, Ablk, Bblk, s);
    for (int kb = 0; kb < NKB; ++kb) {
        CP_WAIT(STAGES - 2);
        __syncthreads();
        const float* buf = smf + (kb % STAGES) * STAGE_FLOATS;
        mma_chunk(buf, buf + 4096, acc, mtb, ntb, lane);
        int nk = kb + STAGES - 1;
        if (nk < NKB) issue_chunk(smb, nk % STAGES, tid, Ablk, Bblk, nk);
    }
    CP_WAIT(0);
}

// ---------------------------------------------------------------------------
// Fused persistent GEMM kernel: 296 CTAs pull tiles from an atomic queue.
// Tiles 0..383: conv (mtile = t/6, ntile = t%6); 384..895: dist (u/8, u%8).
// Dist tiles spin (acquire) on g_done[mtile] == 6 before staging.
// ---------------------------------------------------------------------------
__global__ __launch_bounds__(256, 2) void gemm_fused(const float* __restrict__ bias) {
    extern __shared__ float smf[];
    __shared__ int s_tile;
    const u32 smb = smem_u32(smf);
    const int tid = threadIdx.x, lane = tid & 31, warp = tid >> 5;
    const int mtb = (warp >> 2) * 4, ntb = (warp & 3) * 4;
    const int gid = lane >> 2, tig = lane & 3;

    for (;;) {
        if (tid == 0) s_tile = atomicAdd(&g_ctr, 1);
        __syncthreads();
        const int t = s_tile;
        if (t >= TOTAL_TILES) return;

        float acc[4][4][4];
        #pragma unroll
        for (int i = 0; i < 4; ++i)
            #pragma unroll
            for (int j = 0; j < 4; ++j)
                #pragma unroll
                for (int c = 0; c < 4; ++c) acc[i][j][c] = 0.f;

        if (t < CONV_TILES) {
            // ---------------- conv tile ----------------
            const int mtile = t / 6, ntile = t % 6;
            const int n0 = ntile * 128;
            const float* Ablk = g_Afrag + (size_t)mtile * NKB1 * 4096;
            const float* Bblk = g_Wfrag + (size_t)ntile * NKB1 * 4096;

            run_mainloop<NKB1>(smb, smf, tid, lane, mtb, ntb, Ablk, Bblk, acc);

            // Epilogue: +bias, tf32-split, scatter into dist-A fragment layout.
            const size_t xmb = (size_t)mtile * NKB2 * 4096;
            #pragma unroll
            for (int i = 0; i < 4; ++i) {
                #pragma unroll
                for (int c = 0; c < 4; ++c) {
                    int m = (warp >> 2) * 64 + i * 16 + gid + ((c >> 1) << 3);
                    #pragma unroll
                    for (int j = 0; j < 4; ++j) {
                        int n = n0 + (warp & 3) * 32 + j * 8 + 2 * tig + (c & 1);
                        float x = acc[i][j][c] + __ldg(&bias[n]);
                        float h, md; tf32_split(x, h, md);
                        size_t base = xmb + (size_t)(n >> 4) * 4096;
                        int off = a_off(m, n & 15);
                        g_Xfrag[base + off]        = h;
                        g_Xfrag[base + 2048 + off] = md;
                    }
                }
            }
            __threadfence();
            __syncthreads();
            if (tid == 0) atomicAdd(&g_done[mtile], 1);
        } else {
            // ---------------- dist tile ----------------
            const int u = t - CONV_TILES;
            const int mtile = u / 8, ntile = u % 8;
            const int m0 = mtile * 128, n0 = ntile * 128;

            if (tid == 0) {
                for (;;) {
                    int d;
                    asm volatile("ld.global.acquire.gpu.b32 %0, [%1];"
                                 : "=r"(d) : "l"(&g_done[mtile]) : "memory");
                    if (d >= 6) break;
                    __nanosleep(200);
                }
            }
            __syncthreads();

            const float* Ablk = g_Xfrag  + (size_t)mtile * NKB2 * 4096;
            const float* Bblk = g_CBfrag + (size_t)ntile * NKB2 * 4096;

            run_mainloop<NKB2>(smb, smf, tid, lane, mtb, ntb, Ablk, Bblk, acc);
            __syncthreads();              // stage smem reusable for reduction

            float* redV = smf;            // [128][4]
            int*   redI = (int*)(smf + 512);

            #pragma unroll
            for (int i = 0; i < 4; ++i) {
                #pragma unroll
                for (int h = 0; h < 2; ++h) {
                    float bv = 3.4e38f; int bi = 1 << 30;
                    #pragma unroll
                    for (int j = 0; j < 4; ++j) {
                        #pragma unroll
                        for (int c = 0; c < 2; ++c) {
                            int n = n0 + (warp & 3) * 32 + j * 8 + 2 * tig + c;
                            float v = __ldg(&g_cnorm[n]) - 2.f * acc[i][j][h * 2 + c];
                            if (v < bv || (v == bv && n < bi)) { bv = v; bi = n; }
                        }
                    }
                    #pragma unroll
                    for (int off = 2; off; off >>= 1) {
                        float ov = __shfl_down_sync(0xffffffffu, bv, off, 4);
                        int   oi = __shfl_down_sync(0xffffffffu, bi, off, 4);
                        if (ov < bv || (ov == bv && oi < bi)) { bv = ov; bi = oi; }
                    }
                    if (tig == 0) {
                        int ml = (warp >> 2) * 64 + i * 16 + h * 8 + gid;
                        redV[ml * 4 + (warp & 3)] = bv;
                        redI[ml * 4 + (warp & 3)] = bi;
                    }
                }
            }
            __syncthreads();

            if (tid < 128) {
                float bv = redV[tid * 4]; int bi = redI[tid * 4];
                #pragma unroll
                for (int q = 1; q < 4; ++q) {
                    float v = redV[tid * 4 + q]; int i2 = redI[tid * 4 + q];
                    if (v < bv || (v == bv && i2 < bi)) { bv = v; bi = i2; }
                }
                g_pmin[(size_t)(m0 + tid) * 8 + ntile] = bv;
                g_pidx[(size_t)(m0 + tid) * 8 + ntile] = bi;
            }
            // loop-top __syncthreads orders these reads/writes vs next tile
        }
    }
}

// ---------------------------------------------------------------------------
// Final reduce over the 8 n-tiles per row (lowest index wins ties).
// Output as float32 (harness dtype); indices < 2^24 exact.
// ---------------------------------------------------------------------------
__global__ void final_kernel(float* __restrict__ out) {
    int row = blockIdx.x * blockDim.x + threadIdx.x;
    if (row >= TQ) return;
    float bv = g_pmin[(size_t)row * 8];
    int   bi = g_pidx[(size_t)row * 8];
    #pragma unroll
    for (int t = 1; t < 8; ++t) {
        float v = g_pmin[(size_t)row * 8 + t];
        int   i = g_pidx[(size_t)row * 8 + t];
        if (v < bv || (v == bv && i < bi)) { bv = v; bi = i; }
    }
    out[row] = (float)bi;
}

// ---------------------------------------------------------------------------
// Launch. Inputs resolved BY ELEMENT COUNT (robust to metadata ordering).
// ---------------------------------------------------------------------------
static inline bool size_is(long long got, long long elems) {
    return got == elems || got == elems * 4;
}

extern "C" void kernel_launch(void* const* d_in, const int* in_sizes, int n_in,
                              void* d_out, int out_size) {
    const float* ssl  = nullptr;
    const float* W    = nullptr;
    const float* bias = nullptr;
    const float* cb   = nullptr;

    for (int i = 0; i < n_in; ++i) {
        long long s = (long long)in_sizes[i];
        if      (size_is(s, 8LL * 768 * 16384)) ssl  = (const float*)d_in[i];
        else if (size_is(s, 768LL * 768 * 2))   W    = (const float*)d_in[i];
        else if (size_is(s, 768LL))             bias = (const float*)d_in[i];
        else if (size_is(s, 1024LL * 768))      cb   = (const float*)d_in[i];
    }
    if (!ssl || !W || !bias || !cb) {
        ssl  = (const float*)d_in[0];
        W    = (const float*)d_in[1];
        bias = (const float*)d_in[2];
        cb   = (const float*)d_in[3];
    }
    float* out = (float*)d_out;

    static bool attr_done = false;
    if (!attr_done) {
        cudaFuncSetAttribute(gemm_fused,
                             cudaFuncAttributeMaxDynamicSharedMemorySize, SMEM_BYTES);
        attr_done = true;
    }

    prep_kernel<<<1280, 256>>>(W, cb, ssl);            // also resets queue state
    gemm_fused<<<NWORKERS, 256, SMEM_BYTES>>>(bias);   // persistent, work-queued
    final_kernel<<<TQ / 256, 256>>>(out);
}

// round 14
// speedup vs baseline: 1.0397x; 1.0397x over previous
#include <cuda_runtime.h>
#include <cstdint>

// Problem constants
#define TQ     8192      // T/2 output positions
#define DM     768       // model dim
#define NBINS  1024      // codebook entries
#define TIN    16384     // input T
#define KCONV  1536      // conv GEMM K = D*2
#define NKB1   96        // conv K chunks (1536/16)
#define NKB2   48        // dist K chunks (768/16)

#define CONV_TILES  384              // 64 m-tiles x 6 n-tiles
#define DIST_TILES  512              // 64 m-tiles x 8 n-tiles
#define TOTAL_TILES (CONV_TILES + DIST_TILES)
#define NWORKERS    296              // 148 SMs x 2 CTAs

typedef unsigned int u32;

// ---------------------------------------------------------------------------
// Scratch (__device__ globals; no allocation).
// A operands: [hi 2048][mid 2048] fragment-ordered per (tile, kb).
// B operands: interleaved [k8][nt][lane][bh0 bh1 bm0 bm1] per (tile, kb)
//             -> one LDS.128 yields both hi and mid fragments.
// ---------------------------------------------------------------------------
__device__ float g_Afrag[64 * NKB1 * 4096];   // conv A   (100 MB)
__device__ float g_Wfrag [6 * NKB1 * 4096];   // conv B   (9.4 MB)
__device__ float g_Xfrag[64 * NKB2 * 4096];   // dist A = conv output (50 MB)
__device__ float g_CBfrag[8 * NKB2 * 4096];   // dist B   (6.3 MB)
__device__ float g_cnorm[NBINS];
__device__ float g_pmin[TQ * 8];
__device__ int   g_pidx[TQ * 8];
__device__ int   g_ctr;                        // work-queue counter
__device__ int   g_done[64];                   // conv completions per m-tile

// ---------------------------------------------------------------------------
// Helpers (family-agnostic PTX only — build target is plain sm_103)
// ---------------------------------------------------------------------------
__device__ __forceinline__ void tf32_split(float x, float& h, float& m) {
    u32 hu, mu;
    asm("cvt.rna.tf32.f32 %0, %1;" : "=r"(hu) : "f"(x));
    h = __uint_as_float(hu);
    float r = x - h;
    asm("cvt.rna.tf32.f32 %0, %1;" : "=r"(mu) : "f"(r));
    m = __uint_as_float(mu);
}

__device__ __forceinline__ void mma8(float* d, const u32* a, const u32* b) {
    asm volatile(
        "mma.sync.aligned.m16n8k8.row.col.f32.tf32.tf32.f32 "
        "{%0,%1,%2,%3}, {%4,%5,%6,%7}, {%8,%9}, {%0,%1,%2,%3};"
        : "+f"(d[0]), "+f"(d[1]), "+f"(d[2]), "+f"(d[3])
        : "r"(a[0]), "r"(a[1]), "r"(a[2]), "r"(a[3]), "r"(b[0]), "r"(b[1]));
}

__device__ __forceinline__ u32 smem_u32(const void* p) {
    u32 a;
    asm("{ .reg .u64 t; cvta.to.shared.u64 t, %1; cvt.u32.u64 %0, t; }"
        : "=r"(a) : "l"(p));
    return a;
}
__device__ __forceinline__ void cpasync16(u32 dst, const void* src) {
    asm volatile("cp.async.cg.shared.global [%0], [%1], 16;"
                 :: "r"(dst), "l"(src) : "memory");
}
#define CP_COMMIT() asm volatile("cp.async.commit_group;" ::: "memory")
#define CP_WAIT(n)  asm volatile("cp.async.wait_group %0;" :: "n"(n) : "memory")

// A-fragment offset (m 0..127, k 0..15): hi at off, mid at off+2048
__device__ __forceinline__ int a_off(int m, int k) {
    return ((k >> 3) * 8 + (m >> 4)) * 128
         + ((((m & 7) << 2) | (k & 3)) << 2)
         + (((k >> 2) & 1) << 1) + ((m >> 3) & 1);
}
// B-fragment interleaved offset (n 0..127, k 0..15): hi at off, mid at off+2
__device__ __forceinline__ int b2_off(int n, int k) {
    return (((k >> 3) & 1) << 11) + ((n >> 3) << 7)
         + ((((n & 7) << 2) | (k & 3)) << 2) + ((k >> 2) & 1);
}

// ---------------------------------------------------------------------------
// Unified prep kernel, smem-staged for coalesced gmem I/O.
// One block per 16KB fragment block:
//   b = 0                      : reset queue counters
//   b in [1, 577)              : splitW   (576 = 6 nt x 96 kb)
//   b in [577, 961)            : splitCB  (384 = 8 nt x 48 kb)
//   b in [961, 1089)           : cnorm    (128 blocks, 8 rows each)
//   b in [1089, 7233)          : splitA   (6144 = 64 mt x 96 kb)
// ---------------------------------------------------------------------------
__global__ void prep_kernel(const float* __restrict__ W,
                            const float* __restrict__ cb,
                            const float* __restrict__ ssl) {
    __shared__ float st[4096];
    const int b = blockIdx.x, tid = threadIdx.x;

    if (b == 0) {
        if (tid == 0) g_ctr = 0;
        if (tid < 64) g_done[tid] = 0;
        return;
    }
    if (b < 577) {                                     // splitW -> g_Wfrag
        int item = b - 1, nt = item / NKB1, kb = item % NKB1;
        #pragma unroll
        for (int it = 0; it < 8; ++it) {
            int idx = tid + it * 256;                  // 0..2047
            int row = idx >> 4, kc = idx & 15;
            float h, m;
            tf32_split(W[(size_t)(nt * 128 + row) * KCONV + kb * 16 + kc], h, m);
            int o = b2_off(row, kc);
            st[o] = h; st[o + 2] = m;
        }
        __syncthreads();
        float4* dst = (float4*)(g_Wfrag + ((size_t)nt * NKB1 + kb) * 4096);
        #pragma unroll
        for (int it = 0; it < 4; ++it)
            dst[tid + it * 256] = ((const float4*)st)[tid + it * 256];
    } else if (b < 961) {                              // splitCB -> g_CBfrag
        int item = b - 577, nt = item / NKB2, kb = item % NKB2;
        #pragma unroll
        for (int it = 0; it < 8; ++it) {
            int idx = tid + it * 256;
            int row = idx >> 4, kc = idx & 15;
            float h, m;
            tf32_split(cb[(size_t)(nt * 128 + row) * DM + kb * 16 + kc], h, m);
            int o = b2_off(row, kc);
            st[o] = h; st[o + 2] = m;
        }
        __syncthreads();
        float4* dst = (float4*)(g_CBfrag + ((size_t)nt * NKB2 + kb) * 4096);
        #pragma unroll
        for (int it = 0; it < 4; ++it)
            dst[tid + it * 256] = ((const float4*)st)[tid + it * 256];
    } else if (b < 1089) {                             // cnorm
        int row = (b - 961) * 8 + (tid >> 5);
        int lane = tid & 31;
        const float* r = cb + (size_t)row * DM;
        float s = 0.f;
        for (int i = lane; i < DM; i += 32) { float v = r[i]; s += v * v; }
        #pragma unroll
        for (int o = 16; o; o >>= 1) s += __shfl_xor_sync(0xffffffffu, s, o);
        if (lane == 0) g_cnorm[row] = s;
    } else {                                           // splitA -> g_Afrag
        int item = b - 1089, mt = item / NKB1, kb = item % NKB1;
        #pragma unroll
        for (int it = 0; it < 4; ++it) {
            int idx = tid + it * 256;                  // 0..1023
            int dl = idx >> 7, m = idx & 127;          // dl 0..7
            const float2 v = *(const float2*)(
                ssl + (size_t)(kb * 8 + dl) * TIN + 2 * (mt * 128 + m));
            float h, md;
            tf32_split(v.x, h, md);
            int o = a_off(m, 2 * dl);
            st[o] = h; st[o + 2048] = md;
            tf32_split(v.y, h, md);
            o = a_off(m, 2 * dl + 1);
            st[o] = h; st[o + 2048] = md;
        }
        __syncthreads();
        float4* dst = (float4*)(g_Afrag + ((size_t)mt * NKB1 + kb) * 4096);
        #pragma unroll
        for (int it = 0; it < 4; ++it)
            dst[tid + it * 256] = ((const float4*)st)[tid + it * 256];
    }
}
#define PREP_BLOCKS 7233

// ---------------------------------------------------------------------------
// One BK=16 chunk, 3-pass TF32 split, warp tile 64x32.
// B loads: one LDS.128 per (k8, t) delivers hi+mid fragments (interleaved).
// ---------------------------------------------------------------------------
__device__ __forceinline__ void mma_chunk(const float* As, const float* Bs,
                                          float acc[4][4][4], int mtb, int ntb,
                                          int lane) {
    #pragma unroll
    for (int k8 = 0; k8 < 2; ++k8) {
        uint4 ah[4], am[4]; uint2 bh[4], bm[4];
        #pragma unroll
        for (int t = 0; t < 4; ++t) {
            int base = (k8 * 8 + mtb + t) * 128 + lane * 4;
            ah[t] = *(const uint4*)&As[base];
            am[t] = *(const uint4*)&As[2048 + base];
        }
        #pragma unroll
        for (int t = 0; t < 4; ++t) {
            const uint4 bv = *(const uint4*)&Bs[k8 * 2048 + (ntb + t) * 128 + lane * 4];
            bh[t] = make_uint2(bv.x, bv.y);
            bm[t] = make_uint2(bv.z, bv.w);
        }
        #pragma unroll
        for (int i = 0; i < 4; ++i)
            #pragma unroll
            for (int j = 0; j < 4; ++j)
                mma8(acc[i][j], (const u32*)&ah[i], (const u32*)&bh[j]);
        #pragma unroll
        for (int i = 0; i < 4; ++i)
            #pragma unroll
            for (int j = 0; j < 4; ++j)
                mma8(acc[i][j], (const u32*)&ah[i], (const u32*)&bm[j]);
        #pragma unroll
        for (int i = 0; i < 4; ++i)
            #pragma unroll
            for (int j = 0; j < 4; ++j)
                mma8(acc[i][j], (const u32*)&am[i], (const u32*)&bh[j]);
    }
}

#define STAGES 3
#define STAGE_FLOATS 8192            // A 4096 + B 4096
#define STAGE_BYTES  32768
#define SMEM_BYTES   (STAGES * STAGE_BYTES)   // 96 KB -> 2 CTAs/SM

__device__ __forceinline__ void issue_chunk(u32 smb, int s, int tid,
                                            const float* Ablk, const float* Bblk,
                                            int kb) {
    u32 sb = smb + s * STAGE_BYTES;
    const char* asrc = (const char*)Ablk + (size_t)kb * 16384;
    const char* bsrc = (const char*)Bblk + (size_t)kb * 16384;
    #pragma unroll
    for (int it = 0; it < 4; ++it) {
        int idx = tid + it * 256;
        cpasync16(sb + idx * 16,         asrc + (size_t)idx * 16);
        cpasync16(sb + 16384 + idx * 16, bsrc + (size_t)idx * 16);
    }
    CP_COMMIT();
}

template <int NKB>
__device__ __forceinline__ void run_mainloop(u32 smb, float* smf, int tid,
                                             int lane, int mtb, int ntb,
                                             const float* Ablk, const float* Bblk,
                                             float acc[4][4][4]) {
    #pragma unroll
    for (int s = 0; s < STAGES - 1; ++s) issue_chunk(smb, s, tid, Ablk, Bblk, s);
    for (int kb = 0; kb < NKB; ++kb) {
        CP_WAIT(STAGES - 2);
        __syncthreads();
        const float* buf = smf + (kb % STAGES) * STAGE_FLOATS;
        mma_chunk(buf, buf + 4096, acc, mtb, ntb, lane);
        int nk = kb + STAGES - 1;
        if (nk < NKB) issue_chunk(smb, nk % STAGES, tid, Ablk, Bblk, nk);
    }
    CP_WAIT(0);
}

// ---------------------------------------------------------------------------
// Fused persistent GEMM kernel: 296 CTAs pull tiles from an atomic queue.
// Tiles 0..383: conv (mtile = t/6, ntile = t%6); 384..895: dist (u/8, u%8).
// Dist tiles spin (acquire) on g_done[mtile] == 6 before staging.
// ---------------------------------------------------------------------------
__global__ __launch_bounds__(256, 2) void gemm_fused(const float* __restrict__ bias) {
    extern __shared__ float smf[];
    __shared__ int s_tile;
    const u32 smb = smem_u32(smf);
    const int tid = threadIdx.x, lane = tid & 31, warp = tid >> 5;
    const int mtb = (warp >> 2) * 4, ntb = (warp & 3) * 4;
    const int gid = lane >> 2, tig = lane & 3;

    for (;;) {
        if (tid == 0) s_tile = atomicAdd(&g_ctr, 1);
        __syncthreads();
        const int t = s_tile;
        if (t >= TOTAL_TILES) return;

        float acc[4][4][4];
        #pragma unroll
        for (int i = 0; i < 4; ++i)
            #pragma unroll
            for (int j = 0; j < 4; ++j)
                #pragma unroll
                for (int c = 0; c < 4; ++c) acc[i][j][c] = 0.f;

        if (t < CONV_TILES) {
            // ---------------- conv tile ----------------
            const int mtile = t / 6, ntile = t % 6;
            const int n0 = ntile * 128;
            const float* Ablk = g_Afrag + (size_t)mtile * NKB1 * 4096;
            const float* Bblk = g_Wfrag + (size_t)ntile * NKB1 * 4096;

            run_mainloop<NKB1>(smb, smf, tid, lane, mtb, ntb, Ablk, Bblk, acc);

            // Epilogue: +bias, tf32-split, scatter into dist-A fragment layout.
            const size_t xmb = (size_t)mtile * NKB2 * 4096;
            #pragma unroll
            for (int i = 0; i < 4; ++i) {
                #pragma unroll
                for (int c = 0; c < 4; ++c) {
                    int m = (warp >> 2) * 64 + i * 16 + gid + ((c >> 1) << 3);
                    #pragma unroll
                    for (int j = 0; j < 4; ++j) {
                        int n = n0 + (warp & 3) * 32 + j * 8 + 2 * tig + (c & 1);
                        float x = acc[i][j][c] + __ldg(&bias[n]);
                        float h, md; tf32_split(x, h, md);
                        size_t base = xmb + (size_t)(n >> 4) * 4096;
                        int off = a_off(m, n & 15);
                        g_Xfrag[base + off]        = h;
                        g_Xfrag[base + 2048 + off] = md;
                    }
                }
            }
            __threadfence();
            __syncthreads();
            if (tid == 0) atomicAdd(&g_done[mtile], 1);
        } else {
            // ---------------- dist tile ----------------
            const int u = t - CONV_TILES;
            const int mtile = u / 8, ntile = u % 8;
            const int m0 = mtile * 128, n0 = ntile * 128;

            if (tid == 0) {
                for (;;) {
                    int d;
                    asm volatile("ld.global.acquire.gpu.b32 %0, [%1];"
                                 : "=r"(d) : "l"(&g_done[mtile]) : "memory");
                    if (d >= 6) break;
                    __nanosleep(200);
                }
            }
            __syncthreads();

            const float* Ablk = g_Xfrag  + (size_t)mtile * NKB2 * 4096;
            const float* Bblk = g_CBfrag + (size_t)ntile * NKB2 * 4096;

            run_mainloop<NKB2>(smb, smf, tid, lane, mtb, ntb, Ablk, Bblk, acc);
            __syncthreads();              // stage smem reusable for reduction

            float* redV = smf;            // [128][4]
            int*   redI = (int*)(smf + 512);

            #pragma unroll
            for (int i = 0; i < 4; ++i) {
                #pragma unroll
                for (int h = 0; h < 2; ++h) {
                    float bv = 3.4e38f; int bi = 1 << 30;
                    #pragma unroll
                    for (int j = 0; j < 4; ++j) {
                        #pragma unroll
                        for (int c = 0; c < 2; ++c) {
                            int n = n0 + (warp & 3) * 32 + j * 8 + 2 * tig + c;
                            float v = __ldg(&g_cnorm[n]) - 2.f * acc[i][j][h * 2 + c];
                            if (v < bv || (v == bv && n < bi)) { bv = v; bi = n; }
                        }
                    }
                    #pragma unroll
                    for (int off = 2; off; off >>= 1) {
                        float ov = __shfl_down_sync(0xffffffffu, bv, off, 4);
                        int   oi = __shfl_down_sync(0xffffffffu, bi, off, 4);
                        if (ov < bv || (ov == bv && oi < bi)) { bv = ov; bi = oi; }
                    }
                    if (tig == 0) {
                        int ml = (warp >> 2) * 64 + i * 16 + h * 8 + gid;
                        redV[ml * 4 + (warp & 3)] = bv;
                        redI[ml * 4 + (warp & 3)] = bi;
                    }
                }
            }
            __syncthreads();

            if (tid < 128) {
                float bv = redV[tid * 4]; int bi = redI[tid * 4];
                #pragma unroll
                for (int q = 1; q < 4; ++q) {
                    float v = redV[tid * 4 + q]; int i2 = redI[tid * 4 + q];
                    if (v < bv || (v == bv && i2 < bi)) { bv = v; bi = i2; }
                }
                g_pmin[(size_t)(m0 + tid) * 8 + ntile] = bv;
                g_pidx[(size_t)(m0 + tid) * 8 + ntile] = bi;
            }
            // loop-top __syncthreads orders these reads/writes vs next tile
        }
    }
}

// ---------------------------------------------------------------------------
// Final reduce over the 8 n-tiles per row (lowest index wins ties).
// Output as float32 (harness dtype); indices < 2^24 exact.
// ---------------------------------------------------------------------------
__global__ void final_kernel(float* __restrict__ out) {
    int row = blockIdx.x * blockDim.x + threadIdx.x;
    if (row >= TQ) return;
    float bv = g_pmin[(size_t)row * 8];
    int   bi = g_pidx[(size_t)row * 8];
    #pragma unroll
    for (int t = 1; t < 8; ++t) {
        float v = g_pmin[(size_t)row * 8 + t];
        int   i = g_pidx[(size_t)row * 8 + t];
        if (v < bv || (v == bv && i < bi)) { bv = v; bi = i; }
    }
    out[row] = (float)bi;
}

// ---------------------------------------------------------------------------
// Launch. Inputs resolved BY ELEMENT COUNT (robust to metadata ordering).
// ---------------------------------------------------------------------------
static inline bool size_is(long long got, long long elems) {
    return got == elems || got == elems * 4;
}

extern "C" void kernel_launch(void* const* d_in, const int* in_sizes, int n_in,
                              void* d_out, int out_size) {
    const float* ssl  = nullptr;
    const float* W    = nullptr;
    const float* bias = nullptr;
    const float* cb   = nullptr;

    for (int i = 0; i < n_in; ++i) {
        long long s = (long long)in_sizes[i];
        if      (size_is(s, 8LL * 768 * 16384)) ssl  = (const float*)d_in[i];
        else if (size_is(s, 768LL * 768 * 2))   W    = (const float*)d_in[i];
        else if (size_is(s, 768LL))             bias = (const float*)d_in[i];
        else if (size_is(s, 1024LL * 768))      cb   = (const float*)d_in[i];
    }
    if (!ssl || !W || !bias || !cb) {
        ssl  = (const float*)d_in[0];
        W    = (const float*)d_in[1];
        bias = (const float*)d_in[2];
        cb   = (const float*)d_in[3];
    }
    float* out = (float*)d_out;

    static bool attr_done = false;
    if (!attr_done) {
        cudaFuncSetAttribute(gemm_fused,
                             cudaFuncAttributeMaxDynamicSharedMemorySize, SMEM_BYTES);
        attr_done = true;
    }

    prep_kernel<<<PREP_BLOCKS, 256>>>(W, cb, ssl);     // coalesced, also resets queue
    gemm_fused<<<NWORKERS, 256, SMEM_BYTES>>>(bias);   // persistent, work-queued
    final_kernel<<<TQ / 256, 256>>>(out);
}